// round 7
// baseline (speedup 1.0000x reference)
#include <cuda_runtime.h>
#include <cstdint>

// Problem shape (fixed by the dataset): B=4, S=2048, D=4096
#define DDIM   4096
#define M_ROWS 8192
#define N_ROWS 4096
#define KINT   (DDIM / 4)          // 1024 ints per row

// ---------------- scratch (__device__ globals, allocation-free) ----------------
__device__ __align__(256) int8_t g_qx[(size_t)M_ROWS * DDIM];   // quantized x
__device__ __align__(256) int8_t g_qw[(size_t)N_ROWS * DDIM];   // quantized w
__device__ float g_sa[M_ROWS];   // ax/127 per token row
__device__ float g_sw[N_ROWS];   // aw/127 per output row

// ---------------- PTX helpers ----------------
__device__ __forceinline__ uint32_t smem_u32(const void* p) {
    uint32_t a;
    asm("{ .reg .u64 t; cvta.to.shared.u64 t, %1; cvt.u32.u64 %0, t; }" : "=r"(a) : "l"(p));
    return a;
}
__device__ __forceinline__ void cp4(uint32_t dst, const void* src) {
    asm volatile("cp.async.ca.shared.global [%0], [%1], 4;" :: "r"(dst), "l"(src) : "memory");
}
#define CP_COMMIT()  asm volatile("cp.async.commit_group;" ::: "memory")
#define CP_WAIT(n)   asm volatile("cp.async.wait_group %0;" :: "n"(n) : "memory")

__device__ __forceinline__ void imma16832(int* c, const uint32_t* a, const uint32_t* b) {
    asm volatile(
        "mma.sync.aligned.m16n8k32.row.col.s32.s8.s8.s32 "
        "{%0,%1,%2,%3}, {%4,%5,%6,%7}, {%8,%9}, {%0,%1,%2,%3};\n"
        : "+r"(c[0]), "+r"(c[1]), "+r"(c[2]), "+r"(c[3])
        : "r"(a[0]), "r"(a[1]), "r"(a[2]), "r"(a[3]), "r"(b[0]), "r"(b[1]));
}

// ---------------- fused row-wise absmax int8 quantization ----------------
// Blocks 0..8191: x path (t = x*scales). Blocks 8192..12287: w path (t = w/scales).
__global__ __launch_bounds__(256) void quant_fused_kernel(
    const float* __restrict__ x, const float* __restrict__ w,
    const float* __restrict__ scales)
{
    const int b    = blockIdx.x;
    const bool isx = (b < M_ROWS);
    const int row  = isx ? b : (b - M_ROWS);
    const int tid  = threadIdx.x;
    const float4* src4 = reinterpret_cast<const float4*>((isx ? x : w) + (size_t)row * DDIM);
    const float4* scl4 = reinterpret_cast<const float4*>(scales);

    float v[16];
    float m = 0.f;
    #pragma unroll
    for (int i = 0; i < 4; i++) {
        int g = i * 256 + tid;
        float4 xv = src4[g];
        float4 s  = scl4[g];
        float t0, t1, t2, t3;
        if (isx) { t0 = xv.x * s.x; t1 = xv.y * s.y; t2 = xv.z * s.z; t3 = xv.w * s.w; }
        else     { t0 = xv.x / s.x; t1 = xv.y / s.y; t2 = xv.z / s.z; t3 = xv.w / s.w; }
        v[i*4+0] = t0; v[i*4+1] = t1; v[i*4+2] = t2; v[i*4+3] = t3;
        m = fmaxf(m, fmaxf(fmaxf(fabsf(t0), fabsf(t1)), fmaxf(fabsf(t2), fabsf(t3))));
    }

    __shared__ float red[8];
    #pragma unroll
    for (int o = 16; o > 0; o >>= 1)
        m = fmaxf(m, __shfl_xor_sync(0xffffffffu, m, o));
    if ((tid & 31) == 0) red[tid >> 5] = m;
    __syncthreads();
    if (tid < 32) {
        float t = (tid < 8) ? red[tid] : 0.f;
        #pragma unroll
        for (int o = 4; o > 0; o >>= 1)
            t = fmaxf(t, __shfl_xor_sync(0xffffffffu, t, o));
        if (tid == 0) red[0] = fmaxf(t, 1e-8f);
    }
    __syncthreads();
    const float absmax = red[0];
    const float qs = 127.f / absmax;

    int* qrow = reinterpret_cast<int*>((isx ? g_qx : g_qw) + (size_t)row * DDIM);
    #pragma unroll
    for (int i = 0; i < 4; i++) {
        int g = i * 256 + tid;
        int packed = 0;
        #pragma unroll
        for (int j = 0; j < 4; j++) {
            float t = rintf(v[i*4+j] * qs);
            t = fminf(fmaxf(t, -127.f), 127.f);
            packed |= ((int)t & 0xff) << (8 * j);
        }
        qrow[g] = packed;
    }
    if (tid == 0) {
        if (isx) g_sa[row] = absmax * (1.f / 127.f);
        else     g_sw[row] = absmax * (1.f / 127.f);
    }
}

// ---------------- hybrid GEMM: dp4a warps (n 0-63) + IMMA warps (n 64-127) ----------------
// CTA tile 128x128, K-chunk = 16 ints (64 int8). 3-stage cp.async ring, ONE
// __syncthreads per chunk (barrier after compute(c-1) protects stage (c+2)%3).
// Transposed smem tiles [ki][row], row stride 136 ints (conflict-free for both
// the dp4a int4 row loads and the IMMA scalar fragment loads).
#define NCHUNK (KINT / 16)       // 64
#define TSTR   136               // ints per smem row (128 + 8 pad)
#define STAGE_I (16 * TSTR)      // ints per stage per matrix
#define SMEM_BYTES (3 * 2 * STAGE_I * 4)   // 52224

__global__ __launch_bounds__(256, 2) void gemm_hybrid_kernel(
    const float* __restrict__ bias, const float* __restrict__ scales,
    float* __restrict__ out)
{
    extern __shared__ int smem[];
    int* As = smem;                    // [3][16][TSTR]
    int* Bs = smem + 3 * STAGE_I;      // [3][16][TSTR]

    const int tid  = threadIdx.x;
    const int wid  = tid >> 5;
    const int lane = tid & 31;
    const int m0   = blockIdx.y * 128;
    const int n0   = blockIdx.x * 128;

    const int* qxi = reinterpret_cast<const int*>(g_qx);
    const int* qwi = reinterpret_cast<const int*>(g_qw);
    const uint32_t aBase = smem_u32(As);
    const uint32_t bBase = smem_u32(Bs);

    // stage loader: all 256 threads; 8 x 4B cp.async per matrix per thread.
    auto load_stage = [&](int c) {
        const int s = c % 3;
        #pragma unroll
        for (int j = 0; j < 8; j++) {
            int idx = j * 256 + tid;          // 0..2047
            int m = idx >> 4, ki = idx & 15;
            uint32_t d = (uint32_t)((s * 16 + ki) * TSTR + m) * 4;
            cp4(aBase + d, qxi + (size_t)(m0 + m) * KINT + c * 16 + ki);
            cp4(bBase + d, qwi + (size_t)(n0 + m) * KINT + c * 16 + ki);
        }
    };

    if (wid < 4) {
        // ================= dp4a half: n in [0,64) =================
        const int ty = tid >> 3;      // 0..15 (m)
        const int tx = tid & 7;       // 0..7  (n)
        int acc[8][8];
        #pragma unroll
        for (int i = 0; i < 8; i++)
            #pragma unroll
            for (int j = 0; j < 8; j++) acc[i][j] = 0;

        load_stage(0); CP_COMMIT();
        load_stage(1); CP_COMMIT();
        for (int c = 0; c < NCHUNK; c++) {
            CP_WAIT(1);               // stage c resident (for this thread)
            __syncthreads();          // stage c visible; all done with c-1 => (c+2)%3 free
            if (c + 2 < NCHUNK) load_stage(c + 2);
            CP_COMMIT();
            const int sO = (c % 3) * 16;
            #pragma unroll
            for (int ki = 0; ki < 16; ki++) {
                const int* arow = As + (sO + ki) * TSTR;
                const int* brow = Bs + (sO + ki) * TSTR;
                int a[8], b[8];
                *reinterpret_cast<int4*>(&a[0]) = *reinterpret_cast<const int4*>(arow + ty * 8);
                *reinterpret_cast<int4*>(&a[4]) = *reinterpret_cast<const int4*>(arow + ty * 8 + 4);
                *reinterpret_cast<int4*>(&b[0]) = *reinterpret_cast<const int4*>(brow + tx * 8);
                *reinterpret_cast<int4*>(&b[4]) = *reinterpret_cast<const int4*>(brow + tx * 8 + 4);
                #pragma unroll
                for (int i = 0; i < 8; i++)
                    #pragma unroll
                    for (int j = 0; j < 8; j++)
                        acc[i][j] = __dp4a(a[i], b[j], acc[i][j]);
            }
        }

        // epilogue
        float fw[8], fb[8];
        #pragma unroll
        for (int j = 0; j < 8; j++) {
            int n = n0 + tx * 8 + j;
            fw[j] = g_sw[n];
            fb[j] = __ldg(&bias[n]) / __ldg(&scales[n]);
        }
        #pragma unroll
        for (int i = 0; i < 8; i++) {
            int m = m0 + ty * 8 + i;
            float fa = g_sa[m];
            float4 o0, o1;
            o0.x = acc[i][0]*fa*fw[0]+fb[0]; o0.y = acc[i][1]*fa*fw[1]+fb[1];
            o0.z = acc[i][2]*fa*fw[2]+fb[2]; o0.w = acc[i][3]*fa*fw[3]+fb[3];
            o1.x = acc[i][4]*fa*fw[4]+fb[4]; o1.y = acc[i][5]*fa*fw[5]+fb[5];
            o1.z = acc[i][6]*fa*fw[6]+fb[6]; o1.w = acc[i][7]*fa*fw[7]+fb[7];
            float4* orow = reinterpret_cast<float4*>(out + (size_t)m * N_ROWS + n0 + tx * 8);
            orow[0] = o0; orow[1] = o1;
        }
    } else {
        // ================= IMMA half: n in [64,128) =================
        const int wi  = wid - 4;        // 0..3
        const int wm  = wi >> 1;        // m-offset wm*64
        const int wn  = wi & 1;         // n-offset 64 + wn*32
        const int g   = lane >> 2;
        const int tig = lane & 3;
        int acc[4][4][4];
        #pragma unroll
        for (int i = 0; i < 4; i++)
            #pragma unroll
            for (int j = 0; j < 4; j++)
                #pragma unroll
                for (int k = 0; k < 4; k++) acc[i][j][k] = 0;

        load_stage(0); CP_COMMIT();
        load_stage(1); CP_COMMIT();
        for (int c = 0; c < NCHUNK; c++) {
            CP_WAIT(1);
            __syncthreads();
            if (c + 2 < NCHUNK) load_stage(c + 2);
            CP_COMMIT();
            const int sO = (c % 3) * 16;
            #pragma unroll
            for (int ks = 0; ks < 2; ks++) {
                const int* klor = As + (sO + ks * 8 + tig) * TSTR;
                const int* khir = As + (sO + ks * 8 + tig + 4) * TSTR;
                const int* klob = Bs + (sO + ks * 8 + tig) * TSTR;
                const int* khib = Bs + (sO + ks * 8 + tig + 4) * TSTR;
                uint32_t a[4][4], b[4][2];
                #pragma unroll
                for (int mt = 0; mt < 4; mt++) {
                    int r = wm * 64 + mt * 16 + g;
                    a[mt][0] = (uint32_t)klor[r];
                    a[mt][1] = (uint32_t)klor[r + 8];
                    a[mt][2] = (uint32_t)khir[r];
                    a[mt][3] = (uint32_t)khir[r + 8];
                }
                #pragma unroll
                for (int nt = 0; nt < 4; nt++) {
                    int n = 64 + wn * 32 + nt * 8 + g;
                    b[nt][0] = (uint32_t)klob[n];
                    b[nt][1] = (uint32_t)khib[n];
                }
                #pragma unroll
                for (int mt = 0; mt < 4; mt++)
                    #pragma unroll
                    for (int nt = 0; nt < 4; nt++)
                        imma16832(acc[mt][nt], a[mt], b[nt]);
            }
        }

        // epilogue (C frag: c0 (g,2tig), c1 (g,2tig+1), c2 (g+8,2tig), c3 (g+8,2tig+1))
        float fw[4][2], fb[4][2];
        #pragma unroll
        for (int nt = 0; nt < 4; nt++) {
            int n = n0 + 64 + wn * 32 + nt * 8 + 2 * tig;
            fw[nt][0] = g_sw[n];
            fw[nt][1] = g_sw[n + 1];
            fb[nt][0] = __ldg(&bias[n])     / __ldg(&scales[n]);
            fb[nt][1] = __ldg(&bias[n + 1]) / __ldg(&scales[n + 1]);
        }
        #pragma unroll
        for (int mt = 0; mt < 4; mt++) {
            int mA = m0 + wm * 64 + mt * 16 + g;
            float saA = g_sa[mA];
            float saB = g_sa[mA + 8];
            #pragma unroll
            for (int nt = 0; nt < 4; nt++) {
                int n = n0 + 64 + wn * 32 + nt * 8 + 2 * tig;
                float2 o0, o1;
                o0.x = acc[mt][nt][0] * saA * fw[nt][0] + fb[nt][0];
                o0.y = acc[mt][nt][1] * saA * fw[nt][1] + fb[nt][1];
                o1.x = acc[mt][nt][2] * saB * fw[nt][0] + fb[nt][0];
                o1.y = acc[mt][nt][3] * saB * fw[nt][1] + fb[nt][1];
                *reinterpret_cast<float2*>(out + (size_t)mA       * N_ROWS + n) = o0;
                *reinterpret_cast<float2*>(out + (size_t)(mA + 8) * N_ROWS + n) = o1;
            }
        }
    }
}

// ---------------- launch ----------------
extern "C" void kernel_launch(void* const* d_in, const int* in_sizes, int n_in,
                              void* d_out, int out_size)
{
    const float* x      = (const float*)d_in[0];   // [4,2048,4096]
    const float* weight = (const float*)d_in[1];   // [4096,4096]
    const float* bias   = (const float*)d_in[2];   // [4096]
    const float* scales = (const float*)d_in[3];   // [4096]
    float* out = (float*)d_out;                    // [4,2048,4096]

    cudaFuncSetAttribute(gemm_hybrid_kernel,
                         cudaFuncAttributeMaxDynamicSharedMemorySize, SMEM_BYTES);

    quant_fused_kernel<<<M_ROWS + N_ROWS, 256>>>(x, weight, scales);

    dim3 grid(N_ROWS / 128, M_ROWS / 128);   // (32, 64)
    gemm_hybrid_kernel<<<grid, 256, SMEM_BYTES>>>(bias, scales, out);
}